// round 2
// baseline (speedup 1.0000x reference)
#include <cuda_runtime.h>
#include <cuda_bf16.h>
#include <math.h>

typedef unsigned long long ull;
#define DEVI __device__ __forceinline__

// ---------------- packed f32x2 FFMA2 (sm_103a) ----------------
DEVI void fma2(ull& d, ull a, ull b) {
    asm("fma.rn.f32x2 %0, %1, %2, %0;" : "+l"(d) : "l"(a), "l"(b));
}
DEVI float psum(ull a) {
    float x, y;
    asm("mov.b64 {%0,%1}, %2;" : "=f"(x), "=f"(y) : "l"(a));
    return x + y;
}

// ---------------- activations (precise) ----------------
DEVI float sigm(float x)  { return 1.f / (1.f + expf(-x)); }
DEVI float siluf(float x) { return x / (1.f + expf(-x)); }
DEVI float softpl(float x){ return fmaxf(x, 0.f) + log1pf(expf(-fabsf(x))); }
DEVI float geluf(float x) { return 0.5f * x * (1.f + erff(x * 0.70710678f)); }

// ---------------- problem constants ----------------
#define NBLK 128
#define TB   64
#define NTHR 256

// output element offsets
#define SCAL_OFF 0ull
#define K_OFF    73728ull
#define KI_OFF   81920ull
#define ST0_OFF  90112ull
#define ST1_OFF  67198976ull

// smem layout (floats)
#define HS_OFF   0                         // hs  [64][128]
#define XS_OFF   (HS_OFF + 64*128)         // xss [64][256]  (x-tile in input stage)
#define WS_OFF   (XS_OFF + 64*256)         // ws  [64][132]  (weight tile / w_in)
#define TS_OFF   (WS_OFF + 64*132)         // ts  [64][132]  (pre-LN scratch)
#define BC_OFF   (TS_OFF + 64*132)         // bcs [64][68]   (B|C, later gelu(t1))
#define DTB_OFF  (BC_OFF + 64*68)          // dtB [64][32]
#define YA_OFF   (DTB_OFF + 64*32)         // ya  [64]
#define SMEM_FLOATS (YA_OFF + 64)
#define SMEM_BYTES  (SMEM_FLOATS * 4)

// ---- 64x64 output tile, K=128, f32x2 GEMM. A: smem stride lda. W: smem stride 132.
// Accumulates into vals (caller zero-inits).
DEVI void gemm64(const float* __restrict__ a, int lda, const float* __restrict__ w,
                 float vals[4][4], int tr, int tc) {
    ull acc0[4][4], acc1[4][4];
    #pragma unroll
    for (int i = 0; i < 4; i++)
        #pragma unroll
        for (int j = 0; j < 4; j++) { acc0[i][j] = 0ull; acc1[i][j] = 0ull; }
    #pragma unroll 4
    for (int k = 0; k < 128; k += 4) {
        ulonglong2 av[4], bv[4];
        #pragma unroll
        for (int i = 0; i < 4; i++) av[i] = *(const ulonglong2*)(a + (tr + 16*i)*lda + k);
        #pragma unroll
        for (int j = 0; j < 4; j++) bv[j] = *(const ulonglong2*)(w + (tc + 16*j)*132 + k);
        #pragma unroll
        for (int i = 0; i < 4; i++)
            #pragma unroll
            for (int j = 0; j < 4; j++) {
                fma2(acc0[i][j], av[i].x, bv[j].x);
                fma2(acc1[i][j], av[i].y, bv[j].y);
            }
    }
    #pragma unroll
    for (int i = 0; i < 4; i++)
        #pragma unroll
        for (int j = 0; j < 4; j++) vals[i][j] += psum(acc0[i][j]) + psum(acc1[i][j]);
}

// load a 64-row x 128-col weight slab (global row stride gld) into ws (stride 132)
DEVI void load_ws64(float* ws, const float* __restrict__ g, int gld) {
    #pragma unroll
    for (int t = 0; t < 8; t++) {
        int idx = threadIdx.x + t * NTHR;       // 0..2047
        int r = idx >> 5, kq = idx & 31;
        *(float4*)(ws + r*132 + kq*4) = *(const float4*)(g + r*gld + kq*4);
    }
}

// per-row LayerNorm over 128 cols; warp w owns rows [8w, 8w+8). No internal syncs.
DEVI void do_ln(float* hs, const float* src, int lds,
                const float* __restrict__ g, const float* __restrict__ b, bool addres) {
    int w = threadIdx.x >> 5, lane = threadIdx.x & 31;
    float4 gg = *(const float4*)(g + lane*4);
    float4 bb = *(const float4*)(b + lane*4);
    for (int r = w*8; r < w*8 + 8; r++) {
        float4 v = *(const float4*)(src + r*lds + lane*4);
        if (addres) {
            float4 h = *(const float4*)(hs + r*128 + lane*4);
            v.x += h.x; v.y += h.y; v.z += h.z; v.w += h.w;
        }
        float s = v.x + v.y + v.z + v.w;
        float q = v.x*v.x + v.y*v.y + v.z*v.z + v.w*v.w;
        #pragma unroll
        for (int o = 16; o > 0; o >>= 1) {
            s += __shfl_xor_sync(0xffffffffu, s, o);
            q += __shfl_xor_sync(0xffffffffu, q, o);
        }
        float m   = s * (1.f/128.f);
        float inv = rsqrtf(fmaxf(q * (1.f/128.f) - m*m, 0.f) + 1e-5f);
        float4 o4;
        o4.x = (v.x - m)*inv*gg.x + bb.x;
        o4.y = (v.y - m)*inv*gg.y + bb.y;
        o4.z = (v.z - m)*inv*gg.z + bb.z;
        o4.w = (v.w - m)*inv*gg.w + bb.w;
        *(float4*)(hs + r*128 + lane*4) = o4;
    }
}

__global__ void __launch_bounds__(NTHR, 1) fused_kernel(
    const float* __restrict__ x,      const float* __restrict__ w_in,
    const float* __restrict__ b_in,   const float* __restrict__ ln_in_g,
    const float* __restrict__ ln_in_b,
    const float* __restrict__ in_w0,  const float* __restrict__ Dp0,
    const float* __restrict__ out_w0, const float* __restrict__ ln_g0,
    const float* __restrict__ ln_b0,
    const float* __restrict__ in_w1,  const float* __restrict__ Dp1,
    const float* __restrict__ out_w1, const float* __restrict__ ln_g1,
    const float* __restrict__ ln_b1,
    const float* __restrict__ fn_g,   const float* __restrict__ fn_b,
    const float* __restrict__ sh_w1,  const float* __restrict__ sh_b1,
    const float* __restrict__ sh_w2,  const float* __restrict__ sh_b2,
    const float* __restrict__ k_w,    const float* __restrict__ k_b,
    const float* __restrict__ ki_w,   const float* __restrict__ ki_b,
    float* __restrict__ outp)
{
    extern __shared__ float sm[];
    float* hs   = sm + HS_OFF;
    float* xss  = sm + XS_OFF;
    float* ws   = sm + WS_OFF;
    float* ts   = sm + TS_OFF;
    float* bcs  = sm + BC_OFF;
    float* dtBs = sm + DTB_OFF;
    float* yav  = sm + YA_OFF;

    const int tid = threadIdx.x;
    const int tr = tid >> 4, tc = tid & 15;            // 16x16 thread tile
    const int rowbase = blockIdx.x * TB;

    // ============ input stage: h = LN(x @ w_in^T + b_in) ============
    // x tile -> xss (stride 62), w_in -> ws (stride 62)
    for (int idx = tid; idx < 64*58; idx += NTHR) {
        int r = idx / 58, k = idx - r*58;
        xss[r*62 + k] = x[(size_t)(rowbase + r)*58 + k];
    }
    for (int idx = tid; idx < 128*58; idx += NTHR) {
        int r = idx / 58, k = idx - r*58;
        ws[r*62 + k] = w_in[idx];
    }
    __syncthreads();
    {
        int tc2 = tid & 31, tr2 = tid >> 5;            // 8 rows x 4 cols per thread
        ull acc[8][4];
        #pragma unroll
        for (int i = 0; i < 8; i++)
            #pragma unroll
            for (int j = 0; j < 4; j++) acc[i][j] = 0ull;
        #pragma unroll 1
        for (int k = 0; k < 58; k += 2) {
            ull a[8], b[4];
            #pragma unroll
            for (int i = 0; i < 8; i++) a[i] = *(const ull*)(xss + (tr2 + 8*i)*62 + k);
            #pragma unroll
            for (int j = 0; j < 4; j++) b[j] = *(const ull*)(ws + (tc2 + 32*j)*62 + k);
            #pragma unroll
            for (int i = 0; i < 8; i++)
                #pragma unroll
                for (int j = 0; j < 4; j++) fma2(acc[i][j], a[i], b[j]);
        }
        #pragma unroll
        for (int i = 0; i < 8; i++)
            #pragma unroll
            for (int j = 0; j < 4; j++) {
                int c = tc2 + 32*j;
                ts[(tr2 + 8*i)*132 + c] = psum(acc[i][j]) + __ldg(b_in + c);
            }
    }
    __syncthreads();
    do_ln(hs, ts, 132, ln_in_g, ln_in_b, false);
    __syncthreads();

    // ============ two mamba layers ============
    const float* in_w_l[2]  = {in_w0, in_w1};
    const float* Dp_l[2]    = {Dp0, Dp1};
    const float* out_w_l[2] = {out_w0, out_w1};
    const float* g_l[2]     = {ln_g0, ln_g1};
    const float* b_l[2]     = {ln_b0, ln_b1};
    const ull    soff_l[2]  = {ST0_OFF, ST1_OFF};

    for (int L = 0; L < 2; L++) {
        const float* in_w  = in_w_l[L];
        const float* Dp    = Dp_l[L];
        const float* out_w = out_w_l[L];
        const ull    soff  = soff_l[L];

        // ---- B|C chunk: proj cols 512..575 ----
        load_ws64(ws, in_w + 512*128, 128);
        __syncthreads();
        {
            float vals[4][4] = {};
            gemm64(hs, 128, ws, vals, tr, tc);
            #pragma unroll
            for (int i = 0; i < 4; i++)
                #pragma unroll
                for (int j = 0; j < 4; j++)
                    bcs[(tr + 16*i)*68 + tc + 16*j] = vals[i][j];
        }
        __syncthreads();

        // ---- per-row scalars: dt (col 576), bc = B·C, dtB, ya = dt*bc ----
        if (tid < 64) {
            const float* wdt = in_w + 576*128;
            float acc = 0.f;
            #pragma unroll 4
            for (int kk = 0; kk < 128; kk++) {
                int k = (kk + tid) & 127;              // rotated: conflict-free
                acc += hs[tid*128 + k] * __ldg(wdt + k);
            }
            float dt = softpl(acc);
            float bc = 0.f;
            #pragma unroll
            for (int ss = 0; ss < 32; ss++) {
                int s = (ss + tid) & 31;
                float Bv = bcs[tid*68 + s];
                bc += Bv * bcs[tid*68 + 32 + s];
                dtBs[tid*32 + s] = dt * Bv;
            }
            yav[tid] = dt * bc;
        }

        // ---- x_ssm chunks (proj cols 256..511), with streaming state writes ----
        for (int sub = 0; sub < 4; sub++) {
            __syncthreads();
            load_ws64(ws, in_w + (256 + sub*64)*128, 128);
            __syncthreads();
            float vals[4][4] = {};
            gemm64(hs, 128, ws, vals, tr, tc);
            #pragma unroll
            for (int i = 0; i < 4; i++)
                #pragma unroll
                for (int j = 0; j < 4; j++)
                    xss[(tr + 16*i)*256 + sub*64 + tc + 16*j] = siluf(vals[i][j]);
            __syncthreads();
            // state[b, d, s] = silu(x_ssm)[b,d] * dtB[b,s], coalesced float4 .cs
            float* stbase = outp + soff;
            #pragma unroll 1
            for (int idx = tid; idx < 64*64*8; idx += NTHR) {
                int r   = idx >> 9;                    // row within tile
                int rem = idx & 511;
                int d   = rem >> 3;                    // d within 64-slice
                int sq  = rem & 7;                     // float4 index within 32 states
                float xv  = xss[r*256 + sub*64 + d];
                float4 db = *(const float4*)(dtBs + r*32 + sq*4);
                float4 v; v.x = xv*db.x; v.y = xv*db.y; v.z = xv*db.z; v.w = xv*db.w;
                ull eoff = ((ull)(rowbase + r)*256ull + (ull)(sub*64 + d))*32ull + (ull)(sq*4);
                __stcs((float4*)(stbase + eoff), v);
            }
        }

        // ---- z chunks (proj cols 0..255): u = silu(z) * x_ssm * (ya + Dp) in-place ----
        for (int sub = 0; sub < 4; sub++) {
            __syncthreads();
            load_ws64(ws, in_w + sub*64*128, 128);
            __syncthreads();
            float vals[4][4] = {};
            gemm64(hs, 128, ws, vals, tr, tc);
            #pragma unroll
            for (int i = 0; i < 4; i++)
                #pragma unroll
                for (int j = 0; j < 4; j++) {
                    int r = tr + 16*i, c = sub*64 + tc + 16*j;
                    float xv = xss[r*256 + c];
                    xss[r*256 + c] = siluf(vals[i][j]) * xv * (yav[r] + __ldg(Dp + c));
                }
        }
        __syncthreads();

        // ---- out GEMM: ts = u @ out_w^T (128 cols, K=256 split 2x2) ----
        for (int ch = 0; ch < 2; ch++) {
            float vals[4][4] = {};
            for (int kh = 0; kh < 2; kh++) {
                __syncthreads();
                load_ws64(ws, out_w + (size_t)ch*64*256 + kh*128, 256);
                __syncthreads();
                gemm64(xss + kh*128, 256, ws, vals, tr, tc);
            }
            #pragma unroll
            for (int i = 0; i < 4; i++)
                #pragma unroll
                for (int j = 0; j < 4; j++)
                    ts[(tr + 16*i)*132 + ch*64 + tc + 16*j] = vals[i][j];
        }
        __syncthreads();
        do_ln(hs, ts, 132, g_l[L], b_l[L], true);      // h = LN(h + out)
        __syncthreads();
    }

    // ============ final LN + heads ============
    do_ln(hs, hs, 128, fn_g, fn_b, false);
    __syncthreads();

    // t1 = gelu(h @ sh_w1^T + sh_b1)  -> bcs (stride 68)
    load_ws64(ws, sh_w1, 128);
    __syncthreads();
    {
        float vals[4][4] = {};
        gemm64(hs, 128, ws, vals, tr, tc);
        #pragma unroll
        for (int i = 0; i < 4; i++)
            #pragma unroll
            for (int j = 0; j < 4; j++) {
                int c = tc + 16*j;
                bcs[(tr + 16*i)*68 + c] = geluf(vals[i][j] + __ldg(sh_b1 + c));
            }
    }
    __syncthreads();

    // scaling = softplus(t1 @ sh_w2^T + sh_b2)  (9 cols)
    for (int idx = tid; idx < 64*9; idx += NTHR) {
        int r = idx / 9, c = idx - r*9;
        float acc = __ldg(sh_b2 + c);
        #pragma unroll 4
        for (int ss = 0; ss < 64; ss++) {
            int s = (ss + tid) & 63;
            acc += bcs[r*68 + s] * __ldg(sh_w2 + c*64 + s);
        }
        outp[SCAL_OFF + (ull)(rowbase + r)*9ull + c] = softpl(acc);
    }

    // K, K_internal (per-row dots over h)
    if (tid < 64) {
        float a0 = 0.f, a1 = 0.f;
        #pragma unroll 4
        for (int kk = 0; kk < 128; kk++) {
            int k = (kk + tid) & 127;
            float hv = hs[tid*128 + k];
            a0 += hv * __ldg(k_w + k);
            a1 += hv * __ldg(ki_w + k);
        }
        outp[K_OFF  + (ull)(rowbase + tid)] = sigm(a0 + __ldg(k_b));
        outp[KI_OFF + (ull)(rowbase + tid)] = sigm(a1 + __ldg(ki_b));
    }
}

extern "C" void kernel_launch(void* const* d_in, const int* in_sizes, int n_in,
                              void* d_out, int out_size) {
    (void)in_sizes; (void)n_in; (void)out_size;
    cudaFuncSetAttribute(fused_kernel, cudaFuncAttributeMaxDynamicSharedMemorySize, SMEM_BYTES);
    fused_kernel<<<NBLK, NTHR, SMEM_BYTES>>>(
        (const float*)d_in[0],  (const float*)d_in[1],  (const float*)d_in[2],
        (const float*)d_in[3],  (const float*)d_in[4],
        (const float*)d_in[5],  (const float*)d_in[7],  (const float*)d_in[8],
        (const float*)d_in[9],  (const float*)d_in[10],
        (const float*)d_in[11], (const float*)d_in[13], (const float*)d_in[14],
        (const float*)d_in[15], (const float*)d_in[16],
        (const float*)d_in[17], (const float*)d_in[18],
        (const float*)d_in[19], (const float*)d_in[20],
        (const float*)d_in[21], (const float*)d_in[22],
        (const float*)d_in[23], (const float*)d_in[24],
        (const float*)d_in[25], (const float*)d_in[26],
        (float*)d_out);
}